// round 2
// baseline (speedup 1.0000x reference)
#include <cuda_runtime.h>
#include <math.h>

#define LL 2048
#define DD 64
#define HH 8

// Per-key folded bias coefficients: [k][8] = {A0,A1,A2, B0,B1,B2, s0_3, s1_3}
__device__ float g_pk[LL * 8];

// ---------------------------------------------------------------------------
// Kernel P: fold d_k_top / d_k_bot / d_k_score into per-key coefficients.
// dm[f] = d_q[q,f]*(s0+s1)[k,f] - (kt*s0 + kb*s1)[k,f]   (f<3)
// dm[3] = rt*s0[k,3] + rb*s1[k,3]
// ---------------------------------------------------------------------------
__global__ void prep_kernel(const float* __restrict__ dkt,
                            const float* __restrict__ dkb,
                            const float* __restrict__ dks) {
    int k = blockIdx.x * blockDim.x + threadIdx.x;
    if (k >= LL) return;
    const float* s0 = dks + k * 8;       // [k][0][f]
    const float* s1 = dks + k * 8 + 4;   // [k][1][f]
#pragma unroll
    for (int f = 0; f < 3; f++) {
        g_pk[k * 8 + f]     = s0[f] + s1[f];
        g_pk[k * 8 + 3 + f] = dkt[k * 3 + f] * s0[f] + dkb[k * 3 + f] * s1[f];
    }
    g_pk[k * 8 + 6] = s0[3];
    g_pk[k * 8 + 7] = s1[3];
}

// ---------------------------------------------------------------------------
// Kernel A: scores[h,q,k] = (q.k/8) * softplus(dm.Ww[:,h]) + dm.Wb[:,h]
// 64x64 tile per block, 4x4 register tile per thread. Raw scores -> probs buf.
// ---------------------------------------------------------------------------
__global__ __launch_bounds__(256) void scores_kernel(
    const float* __restrict__ q, const float* __restrict__ kmat,
    const float* __restrict__ dq, const float* __restrict__ rt,
    const float* __restrict__ rb, const float* __restrict__ Ww,
    const float* __restrict__ Wb, float* __restrict__ scores) {
    __shared__ float Qs[64][65];
    __shared__ float Ks[64][65];
    __shared__ float Pk[64][9];
    __shared__ float Dq[64][4];

    const int h = blockIdx.y;
    const int qt = blockIdx.x * 64;
    const int t = threadIdx.x;
    const int tx = t & 15;   // key dim, 4 keys each
    const int ty = t >> 4;   // query dim, 4 rows each

    // Per-head weight columns
    const float ww0 = Ww[0 * HH + h], ww1 = Ww[1 * HH + h];
    const float ww2 = Ww[2 * HH + h], ww3 = Ww[3 * HH + h];
    const float wb0 = Wb[0 * HH + h], wb1 = Wb[1 * HH + h];
    const float wb2 = Wb[2 * HH + h], wb3 = Wb[3 * HH + h];

    // Load Q tile (scale 1/sqrt(64) folded in)
    const float* qbase = q + ((size_t)h * LL + qt) * DD;
    for (int i = t; i < 64 * 16; i += 256) {
        int r = i >> 4, c4 = (i & 15) * 4;
        float4 v4 = *(const float4*)(qbase + r * DD + c4);
        Qs[r][c4 + 0] = v4.x * 0.125f;
        Qs[r][c4 + 1] = v4.y * 0.125f;
        Qs[r][c4 + 2] = v4.z * 0.125f;
        Qs[r][c4 + 3] = v4.w * 0.125f;
    }
    for (int i = t; i < 64 * 3; i += 256) {
        int r = i / 3, f = i % 3;
        Dq[r][f] = dq[(qt + r) * 3 + f];
    }
    __syncthreads();

    float mydq[4][3];
#pragma unroll
    for (int i = 0; i < 4; i++)
#pragma unroll
        for (int f = 0; f < 3; f++) mydq[i][f] = Dq[ty * 4 + i][f];

    for (int kt = 0; kt < LL; kt += 64) {
        __syncthreads();
        const float* kbase = kmat + ((size_t)h * LL + kt) * DD;
        for (int i = t; i < 64 * 16; i += 256) {
            int r = i >> 4, c4 = (i & 15) * 4;
            float4 v4 = *(const float4*)(kbase + r * DD + c4);
            Ks[r][c4 + 0] = v4.x;
            Ks[r][c4 + 1] = v4.y;
            Ks[r][c4 + 2] = v4.z;
            Ks[r][c4 + 3] = v4.w;
        }
        for (int i = t; i < 64 * 8; i += 256) {
            Pk[i >> 3][i & 7] = g_pk[(size_t)(kt + (i >> 3)) * 8 + (i & 7)];
        }
        __syncthreads();

        float acc[4][4];
#pragma unroll
        for (int i = 0; i < 4; i++)
#pragma unroll
            for (int j = 0; j < 4; j++) acc[i][j] = 0.f;

#pragma unroll 8
        for (int d = 0; d < DD; d++) {
            float a0 = Qs[ty * 4 + 0][d], a1 = Qs[ty * 4 + 1][d];
            float a2 = Qs[ty * 4 + 2][d], a3 = Qs[ty * 4 + 3][d];
            float b0 = Ks[tx * 4 + 0][d], b1 = Ks[tx * 4 + 1][d];
            float b2 = Ks[tx * 4 + 2][d], b3 = Ks[tx * 4 + 3][d];
            acc[0][0] += a0 * b0; acc[0][1] += a0 * b1; acc[0][2] += a0 * b2; acc[0][3] += a0 * b3;
            acc[1][0] += a1 * b0; acc[1][1] += a1 * b1; acc[1][2] += a1 * b2; acc[1][3] += a1 * b3;
            acc[2][0] += a2 * b0; acc[2][1] += a2 * b1; acc[2][2] += a2 * b2; acc[2][3] += a2 * b3;
            acc[3][0] += a3 * b0; acc[3][1] += a3 * b1; acc[3][2] += a3 * b2; acc[3][3] += a3 * b3;
        }

        // relative features for my 4 query rows x 4 consecutive keys
        float4 rt4[4], rb4[4];
#pragma unroll
        for (int i = 0; i < 4; i++) {
            int qg = qt + ty * 4 + i;
            rt4[i] = *(const float4*)(rt + (size_t)qg * LL + kt + tx * 4);
            rb4[i] = *(const float4*)(rb + (size_t)qg * LL + kt + tx * 4);
        }

#pragma unroll
        for (int j = 0; j < 4; j++) {
            int kl = tx * 4 + j;
            float A0 = Pk[kl][0], A1 = Pk[kl][1], A2 = Pk[kl][2];
            float B0 = Pk[kl][3], B1 = Pk[kl][4], B2 = Pk[kl][5];
            float s03 = Pk[kl][6], s13 = Pk[kl][7];
#pragma unroll
            for (int i = 0; i < 4; i++) {
                float dm0 = mydq[i][0] * A0 - B0;
                float dm1 = mydq[i][1] * A1 - B1;
                float dm2 = mydq[i][2] * A2 - B2;
                float rtv = (&rt4[i].x)[j];
                float rbv = (&rb4[i].x)[j];
                float dm3 = rtv * s03 + rbv * s13;
                float x = dm0 * ww0 + dm1 * ww1 + dm2 * ww2 + dm3 * ww3;
                float bb = dm0 * wb0 + dm1 * wb1 + dm2 * wb2 + dm3 * wb3;
                float w = (x > 20.f) ? x : log1pf(__expf(x));
                acc[i][j] = acc[i][j] * w + bb;
            }
        }

#pragma unroll
        for (int i = 0; i < 4; i++) {
            int qg = qt + ty * 4 + i;
            float4 o = make_float4(acc[i][0], acc[i][1], acc[i][2], acc[i][3]);
            *(float4*)(scores + ((size_t)(h * LL + qg)) * LL + kt + tx * 4) = o;
        }
    }
}

// ---------------------------------------------------------------------------
// Kernel B: in-place row softmax * c. One block per (h,q) row.
// ---------------------------------------------------------------------------
__global__ __launch_bounds__(256) void softmax_kernel(const float* __restrict__ c,
                                                      float* __restrict__ probs) {
    __shared__ float red[8];
    const size_t row = blockIdx.x;
    float* p = probs + row * LL;
    const int t = threadIdx.x;
    const int lane = t & 31, warp = t >> 5;

    float4 s0 = *(const float4*)(p + t * 4);
    float4 s1 = *(const float4*)(p + 1024 + t * 4);

    float m = fmaxf(fmaxf(fmaxf(s0.x, s0.y), fmaxf(s0.z, s0.w)),
                    fmaxf(fmaxf(s1.x, s1.y), fmaxf(s1.z, s1.w)));
#pragma unroll
    for (int o = 16; o; o >>= 1) m = fmaxf(m, __shfl_xor_sync(0xffffffffu, m, o));
    if (lane == 0) red[warp] = m;
    __syncthreads();
    m = red[0];
#pragma unroll
    for (int i = 1; i < 8; i++) m = fmaxf(m, red[i]);
    __syncthreads();

    float e0x = __expf(s0.x - m), e0y = __expf(s0.y - m);
    float e0z = __expf(s0.z - m), e0w = __expf(s0.w - m);
    float e1x = __expf(s1.x - m), e1y = __expf(s1.y - m);
    float e1z = __expf(s1.z - m), e1w = __expf(s1.w - m);

    float s = e0x + e0y + e0z + e0w + e1x + e1y + e1z + e1w;
#pragma unroll
    for (int o = 16; o; o >>= 1) s += __shfl_xor_sync(0xffffffffu, s, o);
    if (lane == 0) red[warp] = s;
    __syncthreads();
    s = red[0];
#pragma unroll
    for (int i = 1; i < 8; i++) s += red[i];
    float inv = 1.f / s;

    float4 c0 = *(const float4*)(c + t * 4);
    float4 c1 = *(const float4*)(c + 1024 + t * 4);

    *(float4*)(p + t * 4) = make_float4(e0x * inv * c0.x, e0y * inv * c0.y,
                                        e0z * inv * c0.z, e0w * inv * c0.w);
    *(float4*)(p + 1024 + t * 4) = make_float4(e1x * inv * c1.x, e1y * inv * c1.y,
                                               e1z * inv * c1.z, e1w * inv * c1.w);
}

// ---------------------------------------------------------------------------
// Kernel C: out[h,q,d] = sum_k probs[h,q,k] * v[h,k,d]. 64x64 tile per block.
// ---------------------------------------------------------------------------
__global__ __launch_bounds__(256) void pv_kernel(const float* __restrict__ probs,
                                                 const float* __restrict__ v,
                                                 float* __restrict__ out) {
    __shared__ float Ps[64][65];
    __shared__ float Vs[64][65];
    const int h = blockIdx.y;
    const int qt = blockIdx.x * 64;
    const int t = threadIdx.x;
    const int tx = t & 15;   // d dim, 4 each
    const int ty = t >> 4;   // q dim, 4 each

    float acc[4][4];
#pragma unroll
    for (int i = 0; i < 4; i++)
#pragma unroll
        for (int j = 0; j < 4; j++) acc[i][j] = 0.f;

    for (int kt = 0; kt < LL; kt += 64) {
        __syncthreads();
        for (int i = t; i < 64 * 16; i += 256) {
            int r = i >> 4, c4 = (i & 15) * 4;
            float4 a = *(const float4*)(probs + ((size_t)(h * LL + qt + r)) * LL + kt + c4);
            Ps[r][c4 + 0] = a.x; Ps[r][c4 + 1] = a.y;
            Ps[r][c4 + 2] = a.z; Ps[r][c4 + 3] = a.w;
            float4 b = *(const float4*)(v + ((size_t)(h * LL + kt + r)) * DD + c4);
            Vs[r][c4 + 0] = b.x; Vs[r][c4 + 1] = b.y;
            Vs[r][c4 + 2] = b.z; Vs[r][c4 + 3] = b.w;
        }
        __syncthreads();

#pragma unroll 8
        for (int kk = 0; kk < 64; kk++) {
            float a0 = Ps[ty * 4 + 0][kk], a1 = Ps[ty * 4 + 1][kk];
            float a2 = Ps[ty * 4 + 2][kk], a3 = Ps[ty * 4 + 3][kk];
            float b0 = Vs[kk][tx * 4 + 0], b1 = Vs[kk][tx * 4 + 1];
            float b2 = Vs[kk][tx * 4 + 2], b3 = Vs[kk][tx * 4 + 3];
            acc[0][0] += a0 * b0; acc[0][1] += a0 * b1; acc[0][2] += a0 * b2; acc[0][3] += a0 * b3;
            acc[1][0] += a1 * b0; acc[1][1] += a1 * b1; acc[1][2] += a1 * b2; acc[1][3] += a1 * b3;
            acc[2][0] += a2 * b0; acc[2][1] += a2 * b1; acc[2][2] += a2 * b2; acc[2][3] += a2 * b3;
            acc[3][0] += a3 * b0; acc[3][1] += a3 * b1; acc[3][2] += a3 * b2; acc[3][3] += a3 * b3;
        }
    }

#pragma unroll
    for (int i = 0; i < 4; i++) {
        int qg = qt + ty * 4 + i;
        *(float4*)(out + ((size_t)(h * LL + qg)) * DD + tx * 4) =
            make_float4(acc[i][0], acc[i][1], acc[i][2], acc[i][3]);
    }
}

// ---------------------------------------------------------------------------
extern "C" void kernel_launch(void* const* d_in, const int* in_sizes, int n_in,
                              void* d_out, int out_size) {
    const float* q   = (const float*)d_in[0];
    const float* k   = (const float*)d_in[1];
    const float* v   = (const float*)d_in[2];
    const float* c   = (const float*)d_in[3];
    const float* dq  = (const float*)d_in[4];
    const float* dkt = (const float*)d_in[5];
    const float* dkb = (const float*)d_in[6];
    const float* dks = (const float*)d_in[7];
    const float* rt  = (const float*)d_in[8];
    const float* rb  = (const float*)d_in[9];
    const float* Ww  = (const float*)d_in[10];
    const float* Wb  = (const float*)d_in[11];

    float* out   = (float*)d_out;                       // [H, L, D]
    float* probs = (float*)d_out + (size_t)HH * LL * DD; // [H, L, L]

    prep_kernel<<<(LL + 255) / 256, 256>>>(dkt, dkb, dks);

    dim3 gridA(LL / 64, HH);
    scores_kernel<<<gridA, 256>>>(q, k, dq, rt, rb, Ww, Wb, probs);

    softmax_kernel<<<HH * LL, 256>>>(c, probs);

    dim3 gridC(LL / 64, HH);
    pv_kernel<<<gridC, 256>>>(probs, v, out);
}